// round 14
// baseline (speedup 1.0000x reference)
#include <cuda_runtime.h>
#include <cuda_fp16.h>
#include <cstdint>
#include <cstring>

#define HDIM 2048
#define NROWS 8192

// Scratch (allocation-free rule: __device__ globals)
__device__ __half g_y[(size_t)NROWS * HDIM];   // LN outputs (fp16)
__device__ float  g_h[(size_t)NROWS * HDIM];   // GEMM1 output (fp32)
__device__ __half g_w1[(size_t)HDIM * HDIM];   // fp16 W1
__device__ __half g_w2[(size_t)HDIM * HDIM];   // fp16 W2

__device__ __forceinline__ uint32_t h2_bits(__half2 h) {
    uint32_t u;
    memcpy(&u, &h, 4);
    return u;
}

// ---------------------------------------------------------------------------
// LayerNorm: 2 rows per block (256 threads), params reused across rows.
// fp32 in -> fp16 out.  (Verified R12 version.)
// ---------------------------------------------------------------------------
__global__ __launch_bounds__(256) void ln2_kernel(
    const float* __restrict__ in, const float* __restrict__ gamma,
    const float* __restrict__ beta, __half* __restrict__ out)
{
    const int row0 = blockIdx.x * 2;
    const int t = threadIdx.x;

    const float4* gr = reinterpret_cast<const float4*>(gamma);
    const float4* br = reinterpret_cast<const float4*>(beta);
    const float4 ga = gr[t], gb = gr[t + 256];
    const float4 ba = br[t], bb = br[t + 256];

    float4 v0[2], v1[2];
    float s[2], ss[2];
    #pragma unroll
    for (int r = 0; r < 2; r++) {
        const float4* inr = reinterpret_cast<const float4*>(in + (size_t)(row0 + r) * HDIM);
        v0[r] = inr[t];
        v1[r] = inr[t + 256];
        s[r]  = v0[r].x + v0[r].y + v0[r].z + v0[r].w
              + v1[r].x + v1[r].y + v1[r].z + v1[r].w;
        ss[r] = v0[r].x*v0[r].x + v0[r].y*v0[r].y + v0[r].z*v0[r].z + v0[r].w*v0[r].w
              + v1[r].x*v1[r].x + v1[r].y*v1[r].y + v1[r].z*v1[r].z + v1[r].w*v1[r].w;
    }

    #pragma unroll
    for (int o = 16; o > 0; o >>= 1) {
        #pragma unroll
        for (int r = 0; r < 2; r++) {
            s[r]  += __shfl_xor_sync(0xffffffffu, s[r], o);
            ss[r] += __shfl_xor_sync(0xffffffffu, ss[r], o);
        }
    }
    __shared__ float sh_s[8][2], sh_ss[8][2];
    if ((t & 31) == 0) {
        #pragma unroll
        for (int r = 0; r < 2; r++) { sh_s[t >> 5][r] = s[r]; sh_ss[t >> 5][r] = ss[r]; }
    }
    __syncthreads();

    #pragma unroll
    for (int r = 0; r < 2; r++) {
        float tot = 0.f, tot2 = 0.f;
        #pragma unroll
        for (int i = 0; i < 8; i++) { tot += sh_s[i][r]; tot2 += sh_ss[i][r]; }
        const float mu = tot * (1.0f / HDIM);
        const float var = tot2 * (1.0f / HDIM) - mu * mu;
        const float rs = rsqrtf(var + 1e-5f);

        __half2 h0 = __floats2half2_rn((v0[r].x - mu) * rs * ga.x + ba.x,
                                       (v0[r].y - mu) * rs * ga.y + ba.y);
        __half2 h1 = __floats2half2_rn((v0[r].z - mu) * rs * ga.z + ba.z,
                                       (v0[r].w - mu) * rs * ga.w + ba.w);
        __half2 h2 = __floats2half2_rn((v1[r].x - mu) * rs * gb.x + bb.x,
                                       (v1[r].y - mu) * rs * gb.y + bb.y);
        __half2 h3 = __floats2half2_rn((v1[r].z - mu) * rs * gb.z + bb.z,
                                       (v1[r].w - mu) * rs * gb.w + bb.w);
        uint2* outr = reinterpret_cast<uint2*>(out + (size_t)(row0 + r) * HDIM);
        outr[t]       = make_uint2(h2_bits(h0), h2_bits(h1));
        outr[t + 256] = make_uint2(h2_bits(h2), h2_bits(h3));
    }
}

// ---------------------------------------------------------------------------
// Convert both weight matrices to fp16 in one launch. (Verified R12 version.)
// ---------------------------------------------------------------------------
__global__ __launch_bounds__(256) void cvt2_f16_kernel(
    const float* __restrict__ in1, __half* __restrict__ out1,
    const float* __restrict__ in2, __half* __restrict__ out2, int n4)
{
    int i = blockIdx.x * blockDim.x + threadIdx.x;
    const float* in  = (i < n4) ? in1  : in2;
    __half*      out = (i < n4) ? out1 : out2;
    int j = (i < n4) ? i : (i - n4);
    float4 v = reinterpret_cast<const float4*>(in)[j];
    __half2 a = __floats2half2_rn(v.x, v.y);
    __half2 b = __floats2half2_rn(v.z, v.w);
    reinterpret_cast<uint2*>(out)[j] = make_uint2(h2_bits(a), h2_bits(b));
}

// ---------------------------------------------------------------------------
// GEMM: C[M,N] = relu(A@B^T + bias (+resid)), fp16 operands, fp32
// accumulate/out. CTA tile 128x64x64(halves) -> grid 2048 CTAs = 6.92 waves
// (98.8% wave utilization vs 86.5% at BN=128). 4 warps of 64x32 (2x2),
// mma.sync.m16n8k16, ldmatrix.x4 reg double-buffered, 3-stage cp.async,
// SW128 swizzle, one __syncthreads per k-tile, 2 CTAs/SM.
// ---------------------------------------------------------------------------
#define BM 128
#define BN 64
#define BKH 64
#define NSTAGE 3
#define KTILES (HDIM / BKH)           // 32
#define A_STAGE 16384                 // 128 rows * 128B
#define B_STAGE 8192                  // 64 rows * 128B
#define GEMM_SMEM (NSTAGE * (A_STAGE + B_STAGE) + 1024)   // 74752

#define LDSM4(R0, R1, R2, R3, ADDR) \
    asm volatile("ldmatrix.sync.aligned.m8n8.x4.shared.b16 {%0,%1,%2,%3}, [%4];" \
        : "=r"(R0), "=r"(R1), "=r"(R2), "=r"(R3) : "r"(ADDR))

extern __shared__ char gsm[];

__global__ __launch_bounds__(128, 2) void gemm_f16(
    const __half* __restrict__ A, const __half* __restrict__ B,
    const float* __restrict__ bias, const float* __restrict__ resid,
    float* __restrict__ C)
{
    const int K = HDIM, N = HDIM;
    const int tid  = threadIdx.x;
    const int warp = tid >> 5, lane = tid & 31;
    const int wm = warp >> 1, wn = warp & 1;       // 2x2 warps, 64x32 each
    const int gid = lane >> 2, tig = lane & 3;
    const int bm0 = blockIdx.y * BM;
    const int bn0 = blockIdx.x * BN;

    uint32_t sbase = (uint32_t)__cvta_generic_to_shared(gsm);
    sbase = (sbase + 1023) & ~1023u;
    const uint32_t aB = sbase;
    const uint32_t bB = sbase + NSTAGE * A_STAGE;

    const __half* Ag = A + (size_t)bm0 * K;
    const __half* Bg = B + (size_t)bn0 * K;

    auto load_stage = [&](int t) {
        const int s = t % NSTAGE;
        const int k0 = t * BKH;
        #pragma unroll
        for (int i = 0; i < 8; i++) {               // A: 1024 chunks / 128 thr
            int idx = tid + i * 128;
            int r = idx >> 3, c = idx & 7;
            uint32_t dst = aB + s * A_STAGE + r * 128 + ((c ^ (r & 7)) << 4);
            const __half* gp = Ag + (size_t)r * K + k0 + c * 8;
            asm volatile("cp.async.cg.shared.global [%0], [%1], 16;\n" :: "r"(dst), "l"(gp));
        }
        #pragma unroll
        for (int i = 0; i < 4; i++) {               // B: 512 chunks / 128 thr
            int idx = tid + i * 128;
            int r = idx >> 3, c = idx & 7;
            uint32_t dst = bB + s * B_STAGE + r * 128 + ((c ^ (r & 7)) << 4);
            const __half* gp = Bg + (size_t)r * K + k0 + c * 8;
            asm volatile("cp.async.cg.shared.global [%0], [%1], 16;\n" :: "r"(dst), "l"(gp));
        }
    };

    float acc[4][4][4];
    #pragma unroll
    for (int i = 0; i < 4; i++)
        #pragma unroll
        for (int j = 0; j < 4; j++)
            #pragma unroll
            for (int r = 0; r < 4; r++) acc[i][j][r] = 0.f;

    // ldmatrix addressing: A side byte-identical to verified R6; B side is
    // the verified R8 64x32 pattern.
    const int aRow = wm * 64 + (lane & 15);
    const uint32_t aRowOff = (uint32_t)aRow * 128;
    const int aChOff = lane >> 4;
    const int bRow = wn * 32 + ((lane & 7) | ((lane & 16) >> 1));
    const uint32_t bRowOff = (uint32_t)bRow * 128;
    const int bChOff = (lane >> 3) & 1;
    const int swz = lane & 7;

    uint32_t ar[2][4][4], br[2][4][2];

    auto load_frags = [&](uint32_t aS, uint32_t bS, int ks, int buf) {
        #pragma unroll
        for (int fm = 0; fm < 4; fm++) {
            uint32_t addr = aS + aRowOff + fm * 2048 + (uint32_t)(((2 * ks + aChOff) ^ swz) << 4);
            LDSM4(ar[buf][fm][0], ar[buf][fm][1], ar[buf][fm][2], ar[buf][fm][3], addr);
        }
        #pragma unroll
        for (int fb = 0; fb < 2; fb++) {
            uint32_t addr = bS + bRowOff + fb * 2048 + (uint32_t)(((2 * ks + bChOff) ^ swz) << 4);
            LDSM4(br[buf][2*fb][0], br[buf][2*fb][1], br[buf][2*fb+1][0], br[buf][2*fb+1][1], addr);
        }
    };

    load_stage(0);
    asm volatile("cp.async.commit_group;\n");
    load_stage(1);
    asm volatile("cp.async.commit_group;\n");

    for (int kt = 0; kt < KTILES; kt++) {
        asm volatile("cp.async.wait_group 1;\n");
        __syncthreads();

        const int s = kt % NSTAGE;
        const uint32_t aS = aB + s * A_STAGE;
        const uint32_t bS = bB + s * B_STAGE;

        load_frags(aS, bS, 0, 0);
        if (kt + 2 < KTILES) load_stage(kt + 2);
        asm volatile("cp.async.commit_group;\n");

        #pragma unroll
        for (int ks = 0; ks < 4; ks++) {            // 4 x k16 = 64 halves
            const int cur = ks & 1;
            if (ks < 3) load_frags(aS, bS, ks + 1, cur ^ 1);
            #pragma unroll
            for (int fm = 0; fm < 4; fm++)
                #pragma unroll
                for (int fn = 0; fn < 4; fn++) {
                    asm volatile(
                        "mma.sync.aligned.m16n8k16.row.col.f32.f16.f16.f32 "
                        "{%0,%1,%2,%3}, {%4,%5,%6,%7}, {%8,%9}, {%0,%1,%2,%3};\n"
                        : "+f"(acc[fm][fn][0]), "+f"(acc[fm][fn][1]),
                          "+f"(acc[fm][fn][2]), "+f"(acc[fm][fn][3])
                        : "r"(ar[cur][fm][0]), "r"(ar[cur][fm][1]),
                          "r"(ar[cur][fm][2]), "r"(ar[cur][fm][3]),
                          "r"(br[cur][fn][0]), "r"(br[cur][fn][1]));
                }
        }
    }

    // Epilogue: + bias, (+ resid), ReLU
    #pragma unroll
    for (int fm = 0; fm < 4; fm++) {
        const int r0 = bm0 + wm * 64 + fm * 16 + gid;
        const int r1 = r0 + 8;
        #pragma unroll
        for (int fn = 0; fn < 4; fn++) {
            const int col = bn0 + wn * 32 + fn * 8 + 2 * tig;
            const float2 bv = *reinterpret_cast<const float2*>(bias + col);
            float o00 = acc[fm][fn][0] + bv.x;
            float o01 = acc[fm][fn][1] + bv.y;
            float o10 = acc[fm][fn][2] + bv.x;
            float o11 = acc[fm][fn][3] + bv.y;
            if (resid) {
                const float2 x0 = *reinterpret_cast<const float2*>(resid + (size_t)r0 * N + col);
                const float2 x1 = *reinterpret_cast<const float2*>(resid + (size_t)r1 * N + col);
                o00 += x0.x; o01 += x0.y; o10 += x1.x; o11 += x1.y;
            }
            o00 = fmaxf(o00, 0.f); o01 = fmaxf(o01, 0.f);
            o10 = fmaxf(o10, 0.f); o11 = fmaxf(o11, 0.f);
            *reinterpret_cast<float2*>(C + (size_t)r0 * N + col) = make_float2(o00, o01);
            *reinterpret_cast<float2*>(C + (size_t)r1 * N + col) = make_float2(o10, o11);
        }
    }
}

// ---------------------------------------------------------------------------
extern "C" void kernel_launch(void* const* d_in, const int* in_sizes, int n_in,
                              void* d_out, int out_size)
{
    const float* x   = (const float*)d_in[0];
    const float* W1  = (const float*)d_in[1];
    const float* b1  = (const float*)d_in[2];
    const float* W2  = (const float*)d_in[3];
    const float* b2  = (const float*)d_in[4];
    const float* g1  = (const float*)d_in[5];
    const float* be1 = (const float*)d_in[6];
    const float* g2  = (const float*)d_in[7];
    const float* be2 = (const float*)d_in[8];
    float* out = (float*)d_out;

    __half *y, *w1, *w2;
    float *h;
    cudaGetSymbolAddress((void**)&y, g_y);
    cudaGetSymbolAddress((void**)&h, g_h);
    cudaGetSymbolAddress((void**)&w1, g_w1);
    cudaGetSymbolAddress((void**)&w2, g_w2);

    cudaFuncSetAttribute(gemm_f16, cudaFuncAttributeMaxDynamicSharedMemorySize, GEMM_SMEM);

    const int wn4 = HDIM * HDIM / 4;
    dim3 ggrid(HDIM / BN, NROWS / BM);   // (32, 64) = 2048 CTAs

    cvt2_f16_kernel<<<(2 * wn4) / 256, 256>>>(W1, w1, W2, w2, wn4);
    ln2_kernel<<<NROWS / 2, 256>>>(x, g1, be1, y);
    gemm_f16<<<ggrid, 128, GEMM_SMEM>>>(y, w1, b1, nullptr, h);
    ln2_kernel<<<NROWS / 2, 256>>>(h, g2, be2, y);
    gemm_f16<<<ggrid, 128, GEMM_SMEM>>>(y, w2, b2, x, out);
}

// round 15
// speedup vs baseline: 1.0148x; 1.0148x over previous
#include <cuda_runtime.h>
#include <cuda_fp16.h>
#include <cstdint>
#include <cstring>

#define HDIM 2048
#define NROWS 8192

// Scratch (allocation-free rule: __device__ globals)
__device__ __half g_y[(size_t)NROWS * HDIM];   // LN outputs (fp16)
__device__ float  g_h[(size_t)NROWS * HDIM];   // GEMM1 output (fp32)
__device__ __half g_w1[(size_t)HDIM * HDIM];   // fp16 W1
__device__ __half g_w2[(size_t)HDIM * HDIM];   // fp16 W2

__device__ __forceinline__ uint32_t h2_bits(__half2 h) {
    uint32_t u;
    memcpy(&u, &h, 4);
    return u;
}

// ---------------------------------------------------------------------------
// LayerNorm: 2 rows per block (256 threads), params reused across rows.
// fp32 in -> fp16 out.  (Verified R12 version.)
// ---------------------------------------------------------------------------
__global__ __launch_bounds__(256) void ln2_kernel(
    const float* __restrict__ in, const float* __restrict__ gamma,
    const float* __restrict__ beta, __half* __restrict__ out)
{
    const int row0 = blockIdx.x * 2;
    const int t = threadIdx.x;

    const float4* gr = reinterpret_cast<const float4*>(gamma);
    const float4* br = reinterpret_cast<const float4*>(beta);
    const float4 ga = gr[t], gb = gr[t + 256];
    const float4 ba = br[t], bb = br[t + 256];

    float4 v0[2], v1[2];
    float s[2], ss[2];
    #pragma unroll
    for (int r = 0; r < 2; r++) {
        const float4* inr = reinterpret_cast<const float4*>(in + (size_t)(row0 + r) * HDIM);
        v0[r] = inr[t];
        v1[r] = inr[t + 256];
        s[r]  = v0[r].x + v0[r].y + v0[r].z + v0[r].w
              + v1[r].x + v1[r].y + v1[r].z + v1[r].w;
        ss[r] = v0[r].x*v0[r].x + v0[r].y*v0[r].y + v0[r].z*v0[r].z + v0[r].w*v0[r].w
              + v1[r].x*v1[r].x + v1[r].y*v1[r].y + v1[r].z*v1[r].z + v1[r].w*v1[r].w;
    }

    #pragma unroll
    for (int o = 16; o > 0; o >>= 1) {
        #pragma unroll
        for (int r = 0; r < 2; r++) {
            s[r]  += __shfl_xor_sync(0xffffffffu, s[r], o);
            ss[r] += __shfl_xor_sync(0xffffffffu, ss[r], o);
        }
    }
    __shared__ float sh_s[8][2], sh_ss[8][2];
    if ((t & 31) == 0) {
        #pragma unroll
        for (int r = 0; r < 2; r++) { sh_s[t >> 5][r] = s[r]; sh_ss[t >> 5][r] = ss[r]; }
    }
    __syncthreads();

    #pragma unroll
    for (int r = 0; r < 2; r++) {
        float tot = 0.f, tot2 = 0.f;
        #pragma unroll
        for (int i = 0; i < 8; i++) { tot += sh_s[i][r]; tot2 += sh_ss[i][r]; }
        const float mu = tot * (1.0f / HDIM);
        const float var = tot2 * (1.0f / HDIM) - mu * mu;
        const float rs = rsqrtf(var + 1e-5f);

        __half2 h0 = __floats2half2_rn((v0[r].x - mu) * rs * ga.x + ba.x,
                                       (v0[r].y - mu) * rs * ga.y + ba.y);
        __half2 h1 = __floats2half2_rn((v0[r].z - mu) * rs * ga.z + ba.z,
                                       (v0[r].w - mu) * rs * ga.w + ba.w);
        __half2 h2 = __floats2half2_rn((v1[r].x - mu) * rs * gb.x + bb.x,
                                       (v1[r].y - mu) * rs * gb.y + bb.y);
        __half2 h3 = __floats2half2_rn((v1[r].z - mu) * rs * gb.z + bb.z,
                                       (v1[r].w - mu) * rs * gb.w + bb.w);
        uint2* outr = reinterpret_cast<uint2*>(out + (size_t)(row0 + r) * HDIM);
        outr[t]       = make_uint2(h2_bits(h0), h2_bits(h1));
        outr[t + 256] = make_uint2(h2_bits(h2), h2_bits(h3));
    }
}

// ---------------------------------------------------------------------------
// Convert both weight matrices to fp16 in one launch. (Verified R12 version.)
// ---------------------------------------------------------------------------
__global__ __launch_bounds__(256) void cvt2_f16_kernel(
    const float* __restrict__ in1, __half* __restrict__ out1,
    const float* __restrict__ in2, __half* __restrict__ out2, int n4)
{
    int i = blockIdx.x * blockDim.x + threadIdx.x;
    const float* in  = (i < n4) ? in1  : in2;
    __half*      out = (i < n4) ? out1 : out2;
    int j = (i < n4) ? i : (i - n4);
    float4 v = reinterpret_cast<const float4*>(in)[j];
    __half2 a = __floats2half2_rn(v.x, v.y);
    __half2 b = __floats2half2_rn(v.z, v.w);
    reinterpret_cast<uint2*>(out)[j] = make_uint2(h2_bits(a), h2_bits(b));
}

// ---------------------------------------------------------------------------
// GEMM (exact R12 structure): C[M,N] = relu(A@B^T + bias (+resid)), fp16
// operands, fp32 accumulate/out. CTA 128x128x64(halves), 4 warps of 64x64,
// mma.sync.m16n8k16, ldmatrix.x4 reg double-buffered, 3-stage cp.async,
// SW128 swizzle, one __syncthreads per k-tile, 2 CTAs/SM.
// New vs R12: resid lines prefetched to L2, SPREAD across the last 8
// k-tiles (1 line/thread/k-tile) so they land shortly before the epilogue
// without contending with the cp.async ramp.
// ---------------------------------------------------------------------------
#define BM 128
#define BN 128
#define BKH 64
#define NSTAGE 3
#define KTILES (HDIM / BKH)           // 32
#define STAGE_BYTES 16384
#define GEMM_SMEM (NSTAGE * 2 * STAGE_BYTES + 1024)

#define LDSM4(R0, R1, R2, R3, ADDR) \
    asm volatile("ldmatrix.sync.aligned.m8n8.x4.shared.b16 {%0,%1,%2,%3}, [%4];" \
        : "=r"(R0), "=r"(R1), "=r"(R2), "=r"(R3) : "r"(ADDR))

extern __shared__ char gsm[];

__global__ __launch_bounds__(128, 2) void gemm_f16(
    const __half* __restrict__ A, const __half* __restrict__ B,
    const float* __restrict__ bias, const float* __restrict__ resid,
    float* __restrict__ C)
{
    const int K = HDIM, N = HDIM;
    const int tid  = threadIdx.x;
    const int warp = tid >> 5, lane = tid & 31;
    const int wm = warp >> 1, wn = warp & 1;
    const int gid = lane >> 2, tig = lane & 3;
    const int bm0 = blockIdx.y * BM;
    const int bn0 = blockIdx.x * BN;

    uint32_t sbase = (uint32_t)__cvta_generic_to_shared(gsm);
    sbase = (sbase + 1023) & ~1023u;
    const uint32_t aB = sbase;
    const uint32_t bB = sbase + NSTAGE * STAGE_BYTES;

    const __half* Ag = A + (size_t)bm0 * K;
    const __half* Bg = B + (size_t)bn0 * K;

    auto load_stage = [&](int t) {
        const int s = t % NSTAGE;
        const int k0 = t * BKH;
        #pragma unroll
        for (int i = 0; i < 8; i++) {
            int idx = tid + i * 128;
            int r = idx >> 3, c = idx & 7;
            uint32_t dst = aB + s * STAGE_BYTES + r * 128 + ((c ^ (r & 7)) << 4);
            const __half* gp = Ag + (size_t)r * K + k0 + c * 8;
            asm volatile("cp.async.cg.shared.global [%0], [%1], 16;\n" :: "r"(dst), "l"(gp));
        }
        #pragma unroll
        for (int i = 0; i < 8; i++) {
            int idx = tid + i * 128;
            int r = idx >> 3, c = idx & 7;
            uint32_t dst = bB + s * STAGE_BYTES + r * 128 + ((c ^ (r & 7)) << 4);
            const __half* gp = Bg + (size_t)r * K + k0 + c * 8;
            asm volatile("cp.async.cg.shared.global [%0], [%1], 16;\n" :: "r"(dst), "l"(gp));
        }
    };

    float acc[4][8][4];
    #pragma unroll
    for (int i = 0; i < 4; i++)
        #pragma unroll
        for (int j = 0; j < 8; j++)
            #pragma unroll
            for (int r = 0; r < 4; r++) acc[i][j][r] = 0.f;

    const int aRow = wm * 64 + (lane & 15);
    const uint32_t aRowOff = (uint32_t)aRow * 128;
    const int aChOff = lane >> 4;
    const int bRow = wn * 64 + ((lane & 7) | ((lane & 16) >> 1));
    const uint32_t bRowOff = (uint32_t)bRow * 128;
    const int bChOff = (lane >> 3) & 1;
    const int swz = lane & 7;

    uint32_t ar[2][4][4], br[2][8][2];

    auto load_frags = [&](uint32_t aS, uint32_t bS, int ks, int buf) {
        #pragma unroll
        for (int fm = 0; fm < 4; fm++) {
            uint32_t addr = aS + aRowOff + fm * 2048 + (uint32_t)(((2 * ks + aChOff) ^ swz) << 4);
            LDSM4(ar[buf][fm][0], ar[buf][fm][1], ar[buf][fm][2], ar[buf][fm][3], addr);
        }
        #pragma unroll
        for (int fb = 0; fb < 4; fb++) {
            uint32_t addr = bS + bRowOff + fb * 2048 + (uint32_t)(((2 * ks + bChOff) ^ swz) << 4);
            LDSM4(br[buf][2*fb][0], br[buf][2*fb][1], br[buf][2*fb+1][0], br[buf][2*fb+1][1], addr);
        }
    };

    load_stage(0);
    asm volatile("cp.async.commit_group;\n");
    load_stage(1);
    asm volatile("cp.async.commit_group;\n");

    // Spread L2 prefetch of the resid tile over the last 8 k-tiles:
    // 512 lines of 128B total, 64 lines (1/thread) per k-tile.
    const float* rbase = resid ? (resid + (size_t)bm0 * N + bn0) : nullptr;

    for (int kt = 0; kt < KTILES; kt++) {
        asm volatile("cp.async.wait_group 1;\n");
        __syncthreads();

        const int s = kt % NSTAGE;
        const uint32_t aS = aB + s * STAGE_BYTES;
        const uint32_t bS = bB + s * STAGE_BYTES;

        load_frags(aS, bS, 0, 0);
        if (kt + 2 < KTILES) load_stage(kt + 2);
        asm volatile("cp.async.commit_group;\n");

        if (rbase && kt >= KTILES - 8) {
            // phase 0..7; each covers rows [phase*16, phase*16+16), 4 lines/row
            const int phase = kt - (KTILES - 8);
            const int r = phase * 16 + (tid >> 3);      // 16 rows per phase
            const int c = (tid & 7) & 3;                // 4 x 128B lines per row
            // tid&7 in 0..7 but only 4 lines; duplicate coverage is harmless
            asm volatile("prefetch.global.L2 [%0];"
                         :: "l"(rbase + (size_t)r * N + c * 32));
        }

        #pragma unroll
        for (int ks = 0; ks < 4; ks++) {
            const int cur = ks & 1;
            if (ks < 3) load_frags(aS, bS, ks + 1, cur ^ 1);
            #pragma unroll
            for (int fm = 0; fm < 4; fm++)
                #pragma unroll
                for (int fn = 0; fn < 8; fn++) {
                    asm volatile(
                        "mma.sync.aligned.m16n8k16.row.col.f32.f16.f16.f32 "
                        "{%0,%1,%2,%3}, {%4,%5,%6,%7}, {%8,%9}, {%0,%1,%2,%3};\n"
                        : "+f"(acc[fm][fn][0]), "+f"(acc[fm][fn][1]),
                          "+f"(acc[fm][fn][2]), "+f"(acc[fm][fn][3])
                        : "r"(ar[cur][fm][0]), "r"(ar[cur][fm][1]),
                          "r"(ar[cur][fm][2]), "r"(ar[cur][fm][3]),
                          "r"(br[cur][fn][0]), "r"(br[cur][fn][1]));
                }
        }
    }

    // Epilogue: + bias, (+ resid), ReLU
    #pragma unroll
    for (int fm = 0; fm < 4; fm++) {
        const int r0 = bm0 + wm * 64 + fm * 16 + gid;
        const int r1 = r0 + 8;
        #pragma unroll
        for (int fn = 0; fn < 8; fn++) {
            const int col = bn0 + wn * 64 + fn * 8 + 2 * tig;
            const float2 bv = *reinterpret_cast<const float2*>(bias + col);
            float o00 = acc[fm][fn][0] + bv.x;
            float o01 = acc[fm][fn][1] + bv.y;
            float o10 = acc[fm][fn][2] + bv.x;
            float o11 = acc[fm][fn][3] + bv.y;
            if (resid) {
                const float2 x0 = *reinterpret_cast<const float2*>(resid + (size_t)r0 * N + col);
                const float2 x1 = *reinterpret_cast<const float2*>(resid + (size_t)r1 * N + col);
                o00 += x0.x; o01 += x0.y; o10 += x1.x; o11 += x1.y;
            }
            o00 = fmaxf(o00, 0.f); o01 = fmaxf(o01, 0.f);
            o10 = fmaxf(o10, 0.f); o11 = fmaxf(o11, 0.f);
            *reinterpret_cast<float2*>(C + (size_t)r0 * N + col) = make_float2(o00, o01);
            *reinterpret_cast<float2*>(C + (size_t)r1 * N + col) = make_float2(o10, o11);
        }
    }
}

// ---------------------------------------------------------------------------
extern "C" void kernel_launch(void* const* d_in, const int* in_sizes, int n_in,
                              void* d_out, int out_size)
{
    const float* x   = (const float*)d_in[0];
    const float* W1  = (const float*)d_in[1];
    const float* b1  = (const float*)d_in[2];
    const float* W2  = (const float*)d_in[3];
    const float* b2  = (const float*)d_in[4];
    const float* g1  = (const float*)d_in[5];
    const float* be1 = (const float*)d_in[6];
    const float* g2  = (const float*)d_in[7];
    const float* be2 = (const float*)d_in[8];
    float* out = (float*)d_out;

    __half *y, *w1, *w2;
    float *h;
    cudaGetSymbolAddress((void**)&y, g_y);
    cudaGetSymbolAddress((void**)&h, g_h);
    cudaGetSymbolAddress((void**)&w1, g_w1);
    cudaGetSymbolAddress((void**)&w2, g_w2);

    cudaFuncSetAttribute(gemm_f16, cudaFuncAttributeMaxDynamicSharedMemorySize, GEMM_SMEM);

    const int wn4 = HDIM * HDIM / 4;
    dim3 ggrid(HDIM / BN, NROWS / BM);   // (16, 64)

    cvt2_f16_kernel<<<(2 * wn4) / 256, 256>>>(W1, w1, W2, w2, wn4);
    ln2_kernel<<<NROWS / 2, 256>>>(x, g1, be1, y);
    gemm_f16<<<ggrid, 128, GEMM_SMEM>>>(y, w1, b1, nullptr, h);
    ln2_kernel<<<NROWS / 2, 256>>>(h, g2, be2, y);
    gemm_f16<<<ggrid, 128, GEMM_SMEM>>>(y, w2, b2, x, out);
}

// round 16
// speedup vs baseline: 1.0533x; 1.0380x over previous
#include <cuda_runtime.h>
#include <cuda_fp16.h>
#include <cstdint>
#include <cstring>

#define HDIM 2048
#define NROWS 8192

// Scratch (allocation-free rule: __device__ globals)
__device__ __half g_y[(size_t)NROWS * HDIM];   // LN outputs (fp16)
__device__ float  g_h[(size_t)NROWS * HDIM];   // GEMM1 output (fp32)
__device__ __half g_w1[(size_t)HDIM * HDIM];   // fp16 W1
__device__ __half g_w2[(size_t)HDIM * HDIM];   // fp16 W2

__device__ __forceinline__ uint32_t h2_bits(__half2 h) {
    uint32_t u;
    memcpy(&u, &h, 4);
    return u;
}

// ---------------------------------------------------------------------------
// LN body: 2 rows per block (256 threads), params reused. fp32 in, fp16 out.
// (Verified R12 ln2_kernel logic.)
// ---------------------------------------------------------------------------
__device__ __forceinline__ void ln2_body(
    int blk, const float* __restrict__ in, const float* __restrict__ gamma,
    const float* __restrict__ beta, __half* __restrict__ out)
{
    const int row0 = blk * 2;
    const int t = threadIdx.x;

    const float4* gr = reinterpret_cast<const float4*>(gamma);
    const float4* br = reinterpret_cast<const float4*>(beta);
    const float4 ga = gr[t], gb = gr[t + 256];
    const float4 ba = br[t], bb = br[t + 256];

    float4 v0[2], v1[2];
    float s[2], ss[2];
    #pragma unroll
    for (int r = 0; r < 2; r++) {
        const float4* inr = reinterpret_cast<const float4*>(in + (size_t)(row0 + r) * HDIM);
        v0[r] = inr[t];
        v1[r] = inr[t + 256];
        s[r]  = v0[r].x + v0[r].y + v0[r].z + v0[r].w
              + v1[r].x + v1[r].y + v1[r].z + v1[r].w;
        ss[r] = v0[r].x*v0[r].x + v0[r].y*v0[r].y + v0[r].z*v0[r].z + v0[r].w*v0[r].w
              + v1[r].x*v1[r].x + v1[r].y*v1[r].y + v1[r].z*v1[r].z + v1[r].w*v1[r].w;
    }

    #pragma unroll
    for (int o = 16; o > 0; o >>= 1) {
        #pragma unroll
        for (int r = 0; r < 2; r++) {
            s[r]  += __shfl_xor_sync(0xffffffffu, s[r], o);
            ss[r] += __shfl_xor_sync(0xffffffffu, ss[r], o);
        }
    }
    __shared__ float sh_s[8][2], sh_ss[8][2];
    if ((t & 31) == 0) {
        #pragma unroll
        for (int r = 0; r < 2; r++) { sh_s[t >> 5][r] = s[r]; sh_ss[t >> 5][r] = ss[r]; }
    }
    __syncthreads();

    #pragma unroll
    for (int r = 0; r < 2; r++) {
        float tot = 0.f, tot2 = 0.f;
        #pragma unroll
        for (int i = 0; i < 8; i++) { tot += sh_s[i][r]; tot2 += sh_ss[i][r]; }
        const float mu = tot * (1.0f / HDIM);
        const float var = tot2 * (1.0f / HDIM) - mu * mu;
        const float rs = rsqrtf(var + 1e-5f);

        __half2 h0 = __floats2half2_rn((v0[r].x - mu) * rs * ga.x + ba.x,
                                       (v0[r].y - mu) * rs * ga.y + ba.y);
        __half2 h1 = __floats2half2_rn((v0[r].z - mu) * rs * ga.z + ba.z,
                                       (v0[r].w - mu) * rs * ga.w + ba.w);
        __half2 h2 = __floats2half2_rn((v1[r].x - mu) * rs * gb.x + bb.x,
                                       (v1[r].y - mu) * rs * gb.y + bb.y);
        __half2 h3 = __floats2half2_rn((v1[r].z - mu) * rs * gb.z + bb.z,
                                       (v1[r].w - mu) * rs * gb.w + bb.w);
        uint2* outr = reinterpret_cast<uint2*>(out + (size_t)(row0 + r) * HDIM);
        outr[t]       = make_uint2(h2_bits(h0), h2_bits(h1));
        outr[t + 256] = make_uint2(h2_bits(h2), h2_bits(h3));
    }
}

__global__ __launch_bounds__(256) void ln2_kernel(
    const float* __restrict__ in, const float* __restrict__ gamma,
    const float* __restrict__ beta, __half* __restrict__ out)
{
    ln2_body(blockIdx.x, in, gamma, beta, out);
}

// ---------------------------------------------------------------------------
// Fused prologue (verified in R13): blocks [0, 2*CVTB) convert W1/W2 to fp16;
// blocks [2*CVTB, 2*CVTB + NROWS/2) run LN1 on x. Independent work in one
// launch -> the DRAM-streaming cvt and latency-bound LN1 co-schedule
// (~11 us combined vs ~25 us serial).
// ---------------------------------------------------------------------------
#define CVTB (HDIM * HDIM / 4 / 256)     // 4096 blocks per weight matrix

__global__ __launch_bounds__(256) void prologue_kernel(
    const float* __restrict__ W1, __half* __restrict__ w1,
    const float* __restrict__ W2, __half* __restrict__ w2,
    const float* __restrict__ x, const float* __restrict__ gamma,
    const float* __restrict__ beta, __half* __restrict__ y)
{
    const int b = blockIdx.x;
    if (b < 2 * CVTB) {
        const float* in  = (b < CVTB) ? W1 : W2;
        __half*      out = (b < CVTB) ? w1 : w2;
        int j = (b < CVTB ? b : b - CVTB) * 256 + threadIdx.x;
        float4 v = reinterpret_cast<const float4*>(in)[j];
        __half2 a2 = __floats2half2_rn(v.x, v.y);
        __half2 b2 = __floats2half2_rn(v.z, v.w);
        reinterpret_cast<uint2*>(out)[j] = make_uint2(h2_bits(a2), h2_bits(b2));
    } else {
        ln2_body(b - 2 * CVTB, x, gamma, beta, y);
    }
}

// ---------------------------------------------------------------------------
// GEMM (EXACT R12 structure, no prefetch): C[M,N] = relu(A@B^T + bias
// (+resid)), fp16 operands, fp32 accumulate/out. CTA 128x128x64(halves),
// 4 warps of 64x64, mma.sync.m16n8k16, ldmatrix.x4 reg double-buffered,
// 3-stage cp.async, SW128 swizzle, one __syncthreads per k-tile, 2 CTAs/SM.
// ---------------------------------------------------------------------------
#define BM 128
#define BN 128
#define BKH 64
#define NSTAGE 3
#define KTILES (HDIM / BKH)           // 32
#define STAGE_BYTES 16384
#define GEMM_SMEM (NSTAGE * 2 * STAGE_BYTES + 1024)

#define LDSM4(R0, R1, R2, R3, ADDR) \
    asm volatile("ldmatrix.sync.aligned.m8n8.x4.shared.b16 {%0,%1,%2,%3}, [%4];" \
        : "=r"(R0), "=r"(R1), "=r"(R2), "=r"(R3) : "r"(ADDR))

extern __shared__ char gsm[];

__global__ __launch_bounds__(128, 2) void gemm_f16(
    const __half* __restrict__ A, const __half* __restrict__ B,
    const float* __restrict__ bias, const float* __restrict__ resid,
    float* __restrict__ C)
{
    const int K = HDIM, N = HDIM;
    const int tid  = threadIdx.x;
    const int warp = tid >> 5, lane = tid & 31;
    const int wm = warp >> 1, wn = warp & 1;
    const int gid = lane >> 2, tig = lane & 3;
    const int bm0 = blockIdx.y * BM;
    const int bn0 = blockIdx.x * BN;

    uint32_t sbase = (uint32_t)__cvta_generic_to_shared(gsm);
    sbase = (sbase + 1023) & ~1023u;
    const uint32_t aB = sbase;
    const uint32_t bB = sbase + NSTAGE * STAGE_BYTES;

    const __half* Ag = A + (size_t)bm0 * K;
    const __half* Bg = B + (size_t)bn0 * K;

    auto load_stage = [&](int t) {
        const int s = t % NSTAGE;
        const int k0 = t * BKH;
        #pragma unroll
        for (int i = 0; i < 8; i++) {
            int idx = tid + i * 128;
            int r = idx >> 3, c = idx & 7;
            uint32_t dst = aB + s * STAGE_BYTES + r * 128 + ((c ^ (r & 7)) << 4);
            const __half* gp = Ag + (size_t)r * K + k0 + c * 8;
            asm volatile("cp.async.cg.shared.global [%0], [%1], 16;\n" :: "r"(dst), "l"(gp));
        }
        #pragma unroll
        for (int i = 0; i < 8; i++) {
            int idx = tid + i * 128;
            int r = idx >> 3, c = idx & 7;
            uint32_t dst = bB + s * STAGE_BYTES + r * 128 + ((c ^ (r & 7)) << 4);
            const __half* gp = Bg + (size_t)r * K + k0 + c * 8;
            asm volatile("cp.async.cg.shared.global [%0], [%1], 16;\n" :: "r"(dst), "l"(gp));
        }
    };

    float acc[4][8][4];
    #pragma unroll
    for (int i = 0; i < 4; i++)
        #pragma unroll
        for (int j = 0; j < 8; j++)
            #pragma unroll
            for (int r = 0; r < 4; r++) acc[i][j][r] = 0.f;

    const int aRow = wm * 64 + (lane & 15);
    const uint32_t aRowOff = (uint32_t)aRow * 128;
    const int aChOff = lane >> 4;
    const int bRow = wn * 64 + ((lane & 7) | ((lane & 16) >> 1));
    const uint32_t bRowOff = (uint32_t)bRow * 128;
    const int bChOff = (lane >> 3) & 1;
    const int swz = lane & 7;

    uint32_t ar[2][4][4], br[2][8][2];

    auto load_frags = [&](uint32_t aS, uint32_t bS, int ks, int buf) {
        #pragma unroll
        for (int fm = 0; fm < 4; fm++) {
            uint32_t addr = aS + aRowOff + fm * 2048 + (uint32_t)(((2 * ks + aChOff) ^ swz) << 4);
            LDSM4(ar[buf][fm][0], ar[buf][fm][1], ar[buf][fm][2], ar[buf][fm][3], addr);
        }
        #pragma unroll
        for (int fb = 0; fb < 4; fb++) {
            uint32_t addr = bS + bRowOff + fb * 2048 + (uint32_t)(((2 * ks + bChOff) ^ swz) << 4);
            LDSM4(br[buf][2*fb][0], br[buf][2*fb][1], br[buf][2*fb+1][0], br[buf][2*fb+1][1], addr);
        }
    };

    load_stage(0);
    asm volatile("cp.async.commit_group;\n");
    load_stage(1);
    asm volatile("cp.async.commit_group;\n");

    for (int kt = 0; kt < KTILES; kt++) {
        asm volatile("cp.async.wait_group 1;\n");
        __syncthreads();

        const int s = kt % NSTAGE;
        const uint32_t aS = aB + s * STAGE_BYTES;
        const uint32_t bS = bB + s * STAGE_BYTES;

        load_frags(aS, bS, 0, 0);
        if (kt + 2 < KTILES) load_stage(kt + 2);
        asm volatile("cp.async.commit_group;\n");

        #pragma unroll
        for (int ks = 0; ks < 4; ks++) {
            const int cur = ks & 1;
            if (ks < 3) load_frags(aS, bS, ks + 1, cur ^ 1);
            #pragma unroll
            for (int fm = 0; fm < 4; fm++)
                #pragma unroll
                for (int fn = 0; fn < 8; fn++) {
                    asm volatile(
                        "mma.sync.aligned.m16n8k16.row.col.f32.f16.f16.f32 "
                        "{%0,%1,%2,%3}, {%4,%5,%6,%7}, {%8,%9}, {%0,%1,%2,%3};\n"
                        : "+f"(acc[fm][fn][0]), "+f"(acc[fm][fn][1]),
                          "+f"(acc[fm][fn][2]), "+f"(acc[fm][fn][3])
                        : "r"(ar[cur][fm][0]), "r"(ar[cur][fm][1]),
                          "r"(ar[cur][fm][2]), "r"(ar[cur][fm][3]),
                          "r"(br[cur][fn][0]), "r"(br[cur][fn][1]));
                }
        }
    }

    // Epilogue: + bias, (+ resid), ReLU
    #pragma unroll
    for (int fm = 0; fm < 4; fm++) {
        const int r0 = bm0 + wm * 64 + fm * 16 + gid;
        const int r1 = r0 + 8;
        #pragma unroll
        for (int fn = 0; fn < 8; fn++) {
            const int col = bn0 + wn * 64 + fn * 8 + 2 * tig;
            const float2 bv = *reinterpret_cast<const float2*>(bias + col);
            float o00 = acc[fm][fn][0] + bv.x;
            float o01 = acc[fm][fn][1] + bv.y;
            float o10 = acc[fm][fn][2] + bv.x;
            float o11 = acc[fm][fn][3] + bv.y;
            if (resid) {
                const float2 x0 = *reinterpret_cast<const float2*>(resid + (size_t)r0 * N + col);
                const float2 x1 = *reinterpret_cast<const float2*>(resid + (size_t)r1 * N + col);
                o00 += x0.x; o01 += x0.y; o10 += x1.x; o11 += x1.y;
            }
            o00 = fmaxf(o00, 0.f); o01 = fmaxf(o01, 0.f);
            o10 = fmaxf(o10, 0.f); o11 = fmaxf(o11, 0.f);
            *reinterpret_cast<float2*>(C + (size_t)r0 * N + col) = make_float2(o00, o01);
            *reinterpret_cast<float2*>(C + (size_t)r1 * N + col) = make_float2(o10, o11);
        }
    }
}

// ---------------------------------------------------------------------------
extern "C" void kernel_launch(void* const* d_in, const int* in_sizes, int n_in,
                              void* d_out, int out_size)
{
    const float* x   = (const float*)d_in[0];
    const float* W1  = (const float*)d_in[1];
    const float* b1  = (const float*)d_in[2];
    const float* W2  = (const float*)d_in[3];
    const float* b2  = (const float*)d_in[4];
    const float* g1  = (const float*)d_in[5];
    const float* be1 = (const float*)d_in[6];
    const float* g2  = (const float*)d_in[7];
    const float* be2 = (const float*)d_in[8];
    float* out = (float*)d_out;

    __half *y, *w1, *w2;
    float *h;
    cudaGetSymbolAddress((void**)&y, g_y);
    cudaGetSymbolAddress((void**)&h, g_h);
    cudaGetSymbolAddress((void**)&w1, g_w1);
    cudaGetSymbolAddress((void**)&w2, g_w2);

    cudaFuncSetAttribute(gemm_f16, cudaFuncAttributeMaxDynamicSharedMemorySize, GEMM_SMEM);

    dim3 ggrid(HDIM / BN, NROWS / BM);   // (16, 64)

    prologue_kernel<<<2 * CVTB + NROWS / 2, 256>>>(W1, w1, W2, w2, x, g1, be1, y);
    gemm_f16<<<ggrid, 128, GEMM_SMEM>>>(y, w1, b1, nullptr, h);
    ln2_kernel<<<NROWS / 2, 256>>>(h, g2, be2, y);
    gemm_f16<<<ggrid, 128, GEMM_SMEM>>>(y, w2, b2, x, out);
}

// round 17
// speedup vs baseline: 1.0621x; 1.0084x over previous
#include <cuda_runtime.h>
#include <cuda_fp16.h>
#include <cstdint>
#include <cstring>

#define HDIM 2048
#define NROWS 8192

// Scratch (allocation-free rule: __device__ globals)
__device__ __half g_y[(size_t)NROWS * HDIM];   // LN outputs (fp16)
__device__ float  g_h[(size_t)NROWS * HDIM];   // GEMM1 output (fp32)
__device__ __half g_w1[(size_t)HDIM * HDIM];   // fp16 W1
__device__ __half g_w2[(size_t)HDIM * HDIM];   // fp16 W2

__device__ __forceinline__ uint32_t h2_bits(__half2 h) {
    uint32_t u;
    memcpy(&u, &h, 4);
    return u;
}

// ---------------------------------------------------------------------------
// LN body: 2 rows per block (256 threads), params reused. fp32 in, fp16 out.
// (Verified R12/R16 logic.)
// ---------------------------------------------------------------------------
__device__ __forceinline__ void ln2_body(
    int blk, const float* __restrict__ in, const float* __restrict__ gamma,
    const float* __restrict__ beta, __half* __restrict__ out)
{
    const int row0 = blk * 2;
    const int t = threadIdx.x;

    const float4* gr = reinterpret_cast<const float4*>(gamma);
    const float4* br = reinterpret_cast<const float4*>(beta);
    const float4 ga = gr[t], gb = gr[t + 256];
    const float4 ba = br[t], bb = br[t + 256];

    float4 v0[2], v1[2];
    float s[2], ss[2];
    #pragma unroll
    for (int r = 0; r < 2; r++) {
        const float4* inr = reinterpret_cast<const float4*>(in + (size_t)(row0 + r) * HDIM);
        v0[r] = inr[t];
        v1[r] = inr[t + 256];
        s[r]  = v0[r].x + v0[r].y + v0[r].z + v0[r].w
              + v1[r].x + v1[r].y + v1[r].z + v1[r].w;
        ss[r] = v0[r].x*v0[r].x + v0[r].y*v0[r].y + v0[r].z*v0[r].z + v0[r].w*v0[r].w
              + v1[r].x*v1[r].x + v1[r].y*v1[r].y + v1[r].z*v1[r].z + v1[r].w*v1[r].w;
    }

    #pragma unroll
    for (int o = 16; o > 0; o >>= 1) {
        #pragma unroll
        for (int r = 0; r < 2; r++) {
            s[r]  += __shfl_xor_sync(0xffffffffu, s[r], o);
            ss[r] += __shfl_xor_sync(0xffffffffu, ss[r], o);
        }
    }
    __shared__ float sh_s[8][2], sh_ss[8][2];
    if ((t & 31) == 0) {
        #pragma unroll
        for (int r = 0; r < 2; r++) { sh_s[t >> 5][r] = s[r]; sh_ss[t >> 5][r] = ss[r]; }
    }
    __syncthreads();

    #pragma unroll
    for (int r = 0; r < 2; r++) {
        float tot = 0.f, tot2 = 0.f;
        #pragma unroll
        for (int i = 0; i < 8; i++) { tot += sh_s[i][r]; tot2 += sh_ss[i][r]; }
        const float mu = tot * (1.0f / HDIM);
        const float var = tot2 * (1.0f / HDIM) - mu * mu;
        const float rs = rsqrtf(var + 1e-5f);

        __half2 h0 = __floats2half2_rn((v0[r].x - mu) * rs * ga.x + ba.x,
                                       (v0[r].y - mu) * rs * ga.y + ba.y);
        __half2 h1 = __floats2half2_rn((v0[r].z - mu) * rs * ga.z + ba.z,
                                       (v0[r].w - mu) * rs * ga.w + ba.w);
        __half2 h2 = __floats2half2_rn((v1[r].x - mu) * rs * gb.x + bb.x,
                                       (v1[r].y - mu) * rs * gb.y + bb.y);
        __half2 h3 = __floats2half2_rn((v1[r].z - mu) * rs * gb.z + bb.z,
                                       (v1[r].w - mu) * rs * gb.w + bb.w);
        uint2* outr = reinterpret_cast<uint2*>(out + (size_t)(row0 + r) * HDIM);
        outr[t]       = make_uint2(h2_bits(h0), h2_bits(h1));
        outr[t + 256] = make_uint2(h2_bits(h2), h2_bits(h3));
    }
}

__global__ __launch_bounds__(256) void ln2_kernel(
    const float* __restrict__ in, const float* __restrict__ gamma,
    const float* __restrict__ beta, __half* __restrict__ out)
{
    ln2_body(blockIdx.x, in, gamma, beta, out);
}

// ---------------------------------------------------------------------------
// Fused prologue (verified R16): blocks [0, 2*CVTB) convert W1/W2 to fp16;
// blocks [2*CVTB, 2*CVTB + NROWS/2) run LN1 on x.
// ---------------------------------------------------------------------------
#define CVTB (HDIM * HDIM / 4 / 256)     // 4096 blocks per weight matrix

__global__ __launch_bounds__(256) void prologue_kernel(
    const float* __restrict__ W1, __half* __restrict__ w1,
    const float* __restrict__ W2, __half* __restrict__ w2,
    const float* __restrict__ x, const float* __restrict__ gamma,
    const float* __restrict__ beta, __half* __restrict__ y)
{
    const int b = blockIdx.x;
    if (b < 2 * CVTB) {
        const float* in  = (b < CVTB) ? W1 : W2;
        __half*      out = (b < CVTB) ? w1 : w2;
        int j = (b < CVTB ? b : b - CVTB) * 256 + threadIdx.x;
        float4 v = reinterpret_cast<const float4*>(in)[j];
        __half2 a2 = __floats2half2_rn(v.x, v.y);
        __half2 b2 = __floats2half2_rn(v.z, v.w);
        reinterpret_cast<uint2*>(out)[j] = make_uint2(h2_bits(a2), h2_bits(b2));
    } else {
        ln2_body(b - 2 * CVTB, x, gamma, beta, y);
    }
}

// ---------------------------------------------------------------------------
// GEMM (R16 structure; ONLY change: reversed M-tile raster so wave 1 reads
// the freshest-written A rows, aligning producer/consumer L2 temporality):
// C[M,N] = relu(A@B^T + bias (+resid)), fp16 operands, fp32 accumulate/out.
// CTA 128x128x64(halves), 4 warps of 64x64, mma.sync.m16n8k16, ldmatrix.x4
// reg double-buffered, 3-stage cp.async, SW128 swizzle, 2 CTAs/SM.
// ---------------------------------------------------------------------------
#define BM 128
#define BN 128
#define BKH 64
#define NSTAGE 3
#define KTILES (HDIM / BKH)           // 32
#define STAGE_BYTES 16384
#define GEMM_SMEM (NSTAGE * 2 * STAGE_BYTES + 1024)

#define LDSM4(R0, R1, R2, R3, ADDR) \
    asm volatile("ldmatrix.sync.aligned.m8n8.x4.shared.b16 {%0,%1,%2,%3}, [%4];" \
        : "=r"(R0), "=r"(R1), "=r"(R2), "=r"(R3) : "r"(ADDR))

extern __shared__ char gsm[];

__global__ __launch_bounds__(128, 2) void gemm_f16(
    const __half* __restrict__ A, const __half* __restrict__ B,
    const float* __restrict__ bias, const float* __restrict__ resid,
    float* __restrict__ C)
{
    const int K = HDIM, N = HDIM;
    const int tid  = threadIdx.x;
    const int warp = tid >> 5, lane = tid & 31;
    const int wm = warp >> 1, wn = warp & 1;
    const int gid = lane >> 2, tig = lane & 3;
    // Reversed M raster: first-scheduled CTAs take the highest (hottest) rows.
    const int bm0 = (gridDim.y - 1 - blockIdx.y) * BM;
    const int bn0 = blockIdx.x * BN;

    uint32_t sbase = (uint32_t)__cvta_generic_to_shared(gsm);
    sbase = (sbase + 1023) & ~1023u;
    const uint32_t aB = sbase;
    const uint32_t bB = sbase + NSTAGE * STAGE_BYTES;

    const __half* Ag = A + (size_t)bm0 * K;
    const __half* Bg = B + (size_t)bn0 * K;

    auto load_stage = [&](int t) {
        const int s = t % NSTAGE;
        const int k0 = t * BKH;
        #pragma unroll
        for (int i = 0; i < 8; i++) {
            int idx = tid + i * 128;
            int r = idx >> 3, c = idx & 7;
            uint32_t dst = aB + s * STAGE_BYTES + r * 128 + ((c ^ (r & 7)) << 4);
            const __half* gp = Ag + (size_t)r * K + k0 + c * 8;
            asm volatile("cp.async.cg.shared.global [%0], [%1], 16;\n" :: "r"(dst), "l"(gp));
        }
        #pragma unroll
        for (int i = 0; i < 8; i++) {
            int idx = tid + i * 128;
            int r = idx >> 3, c = idx & 7;
            uint32_t dst = bB + s * STAGE_BYTES + r * 128 + ((c ^ (r & 7)) << 4);
            const __half* gp = Bg + (size_t)r * K + k0 + c * 8;
            asm volatile("cp.async.cg.shared.global [%0], [%1], 16;\n" :: "r"(dst), "l"(gp));
        }
    };

    float acc[4][8][4];
    #pragma unroll
    for (int i = 0; i < 4; i++)
        #pragma unroll
        for (int j = 0; j < 8; j++)
            #pragma unroll
            for (int r = 0; r < 4; r++) acc[i][j][r] = 0.f;

    const int aRow = wm * 64 + (lane & 15);
    const uint32_t aRowOff = (uint32_t)aRow * 128;
    const int aChOff = lane >> 4;
    const int bRow = wn * 64 + ((lane & 7) | ((lane & 16) >> 1));
    const uint32_t bRowOff = (uint32_t)bRow * 128;
    const int bChOff = (lane >> 3) & 1;
    const int swz = lane & 7;

    uint32_t ar[2][4][4], br[2][8][2];

    auto load_frags = [&](uint32_t aS, uint32_t bS, int ks, int buf) {
        #pragma unroll
        for (int fm = 0; fm < 4; fm++) {
            uint32_t addr = aS + aRowOff + fm * 2048 + (uint32_t)(((2 * ks + aChOff) ^ swz) << 4);
            LDSM4(ar[buf][fm][0], ar[buf][fm][1], ar[buf][fm][2], ar[buf][fm][3], addr);
        }
        #pragma unroll
        for (int fb = 0; fb < 4; fb++) {
            uint32_t addr = bS + bRowOff + fb * 2048 + (uint32_t)(((2 * ks + bChOff) ^ swz) << 4);
            LDSM4(br[buf][2*fb][0], br[buf][2*fb][1], br[buf][2*fb+1][0], br[buf][2*fb+1][1], addr);
        }
    };

    load_stage(0);
    asm volatile("cp.async.commit_group;\n");
    load_stage(1);
    asm volatile("cp.async.commit_group;\n");

    for (int kt = 0; kt < KTILES; kt++) {
        asm volatile("cp.async.wait_group 1;\n");
        __syncthreads();

        const int s = kt % NSTAGE;
        const uint32_t aS = aB + s * STAGE_BYTES;
        const uint32_t bS = bB + s * STAGE_BYTES;

        load_frags(aS, bS, 0, 0);
        if (kt + 2 < KTILES) load_stage(kt + 2);
        asm volatile("cp.async.commit_group;\n");

        #pragma unroll
        for (int ks = 0; ks < 4; ks++) {
            const int cur = ks & 1;
            if (ks < 3) load_frags(aS, bS, ks + 1, cur ^ 1);
            #pragma unroll
            for (int fm = 0; fm < 4; fm++)
                #pragma unroll
                for (int fn = 0; fn < 8; fn++) {
                    asm volatile(
                        "mma.sync.aligned.m16n8k16.row.col.f32.f16.f16.f32 "
                        "{%0,%1,%2,%3}, {%4,%5,%6,%7}, {%8,%9}, {%0,%1,%2,%3};\n"
                        : "+f"(acc[fm][fn][0]), "+f"(acc[fm][fn][1]),
                          "+f"(acc[fm][fn][2]), "+f"(acc[fm][fn][3])
                        : "r"(ar[cur][fm][0]), "r"(ar[cur][fm][1]),
                          "r"(ar[cur][fm][2]), "r"(ar[cur][fm][3]),
                          "r"(br[cur][fn][0]), "r"(br[cur][fn][1]));
                }
        }
    }

    // Epilogue: + bias, (+ resid), ReLU
    #pragma unroll
    for (int fm = 0; fm < 4; fm++) {
        const int r0 = bm0 + wm * 64 + fm * 16 + gid;
        const int r1 = r0 + 8;
        #pragma unroll
        for (int fn = 0; fn < 8; fn++) {
            const int col = bn0 + wn * 64 + fn * 8 + 2 * tig;
            const float2 bv = *reinterpret_cast<const float2*>(bias + col);
            float o00 = acc[fm][fn][0] + bv.x;
            float o01 = acc[fm][fn][1] + bv.y;
            float o10 = acc[fm][fn][2] + bv.x;
            float o11 = acc[fm][fn][3] + bv.y;
            if (resid) {
                const float2 x0 = *reinterpret_cast<const float2*>(resid + (size_t)r0 * N + col);
                const float2 x1 = *reinterpret_cast<const float2*>(resid + (size_t)r1 * N + col);
                o00 += x0.x; o01 += x0.y; o10 += x1.x; o11 += x1.y;
            }
            o00 = fmaxf(o00, 0.f); o01 = fmaxf(o01, 0.f);
            o10 = fmaxf(o10, 0.f); o11 = fmaxf(o11, 0.f);
            *reinterpret_cast<float2*>(C + (size_t)r0 * N + col) = make_float2(o00, o01);
            *reinterpret_cast<float2*>(C + (size_t)r1 * N + col) = make_float2(o10, o11);
        }
    }
}

// ---------------------------------------------------------------------------
extern "C" void kernel_launch(void* const* d_in, const int* in_sizes, int n_in,
                              void* d_out, int out_size)
{
    const float* x   = (const float*)d_in[0];
    const float* W1  = (const float*)d_in[1];
    const float* b1  = (const float*)d_in[2];
    const float* W2  = (const float*)d_in[3];
    const float* b2  = (const float*)d_in[4];
    const float* g1  = (const float*)d_in[5];
    const float* be1 = (const float*)d_in[6];
    const float* g2  = (const float*)d_in[7];
    const float* be2 = (const float*)d_in[8];
    float* out = (float*)d_out;

    __half *y, *w1, *w2;
    float *h;
    cudaGetSymbolAddress((void**)&y, g_y);
    cudaGetSymbolAddress((void**)&h, g_h);
    cudaGetSymbolAddress((void**)&w1, g_w1);
    cudaGetSymbolAddress((void**)&w2, g_w2);

    cudaFuncSetAttribute(gemm_f16, cudaFuncAttributeMaxDynamicSharedMemorySize, GEMM_SMEM);

    dim3 ggrid(HDIM / BN, NROWS / BM);   // (16, 64)

    prologue_kernel<<<2 * CVTB + NROWS / 2, 256>>>(W1, w1, W2, w2, x, g1, be1, y);
    gemm_f16<<<ggrid, 128, GEMM_SMEM>>>(y, w1, b1, nullptr, h);
    ln2_kernel<<<NROWS / 2, 256>>>(h, g2, be2, y);
    gemm_f16<<<ggrid, 128, GEMM_SMEM>>>(y, w2, b2, x, out);
}